// round 3
// baseline (speedup 1.0000x reference)
#include <cuda_runtime.h>

#define NW   10
#define QDIM 1024
#define NBLK 4
#define WPB  4                    // warps (batch elements) per CTA
#define NTHREADS (WPB * 32)

typedef unsigned long long u64;

// Packed-complex diag tables: {c, c, -s, s} so that
// cmul(a, (c,s)) = a*{c,c} + swap(a)*{-s,s}   (2 x f32x2 ops)
__device__ float4 gA[NBLK][QDIM];
__device__ float4 gB[NBLK][QDIM];
__device__ float4 gC[NBLK][QDIM];
__device__ float2 gRy[NBLK][2][NW];   // (cos(th/2), sin(th/2))

// CX-ring permutation, closed form (GF(2)-linear):
// out_i = b_i ^ b_{i+1} (i=0..7), out8 = b8^b9^b0, out9 = b9^b0
__host__ __device__ __forceinline__ int perm_of(int s) {
    int lo = (s ^ (s >> 1)) & 0xFF;
    int b0 = s & 1, b8 = (s >> 8) & 1, b9 = (s >> 9) & 1;
    return lo | ((b8 ^ b9 ^ b0) << 8) | ((b9 ^ b0) << 9);
}

__device__ __forceinline__ float dotz(const float* __restrict__ p, int s) {
    float d = 0.f;
    #pragma unroll
    for (int w = 0; w < NW; ++w)
        d += ((s >> (9 - w)) & 1) ? -p[w] : p[w];
    return d;
}

__global__ void precompute_kernel(const float* __restrict__ params) {
    int s = threadIdx.x;                          // 0..1023
    if (s < NBLK * 2 * NW) {                      // RY coefficient table
        int k = s / (2 * NW), r = s % (2 * NW);
        int sweep = r / NW, w = r % NW;
        float th = params[(k * 6 + (sweep ? 4 : 1)) * NW + w];
        gRy[k][sweep][w] = make_float2(cosf(0.5f * th), sinf(0.5f * th));
    }
    int ps = perm_of(s);
    #pragma unroll
    for (int k = 0; k < NBLK; ++k) {
        const float* p = params + k * 6 * NW;
        float aA = dotz(p + 0 * NW, s);
        float aB = dotz(p + 3 * NW, s) + dotz(p + 2 * NW, ps);
        float aC = dotz(p + 5 * NW, ps);
        float c, si;
        sincosf(-0.5f * aA, &si, &c); gA[k][s] = make_float4(c, c, -si, si);
        sincosf(-0.5f * aB, &si, &c); gB[k][s] = make_float4(c, c, -si, si);
        sincosf(-0.5f * aC, &si, &c); gC[k][s] = make_float4(c, c, -si, si);
    }
}

// ---- packed f32x2 helpers (sm_103a; ptxas never auto-fuses these) ----
__device__ __forceinline__ u64 pk2(float x, float y) {
    u64 r; asm("mov.b64 %0, {%1, %2};" : "=l"(r) : "f"(x), "f"(y)); return r;
}
__device__ __forceinline__ void unpk2(u64 v, float& x, float& y) {
    asm("mov.b64 {%0, %1}, %2;" : "=f"(x), "=f"(y) : "l"(v));
}
__device__ __forceinline__ u64 swap2(u64 v) {
    float x, y; unpk2(v, x, y); return pk2(y, x);
}
__device__ __forceinline__ u64 mul2(u64 a, u64 b) {
    u64 r; asm("mul.rn.f32x2 %0, %1, %2;" : "=l"(r) : "l"(a), "l"(b)); return r;
}
__device__ __forceinline__ u64 fma2(u64 a, u64 b, u64 c) {
    u64 r; asm("fma.rn.f32x2 %0, %1, %2, %3;" : "=l"(r) : "l"(a), "l"(b), "l"(c)); return r;
}
// complex mul by table entry T = {c, c, -s, s}
__device__ __forceinline__ u64 cmulT(u64 a, float4 T) {
    return fma2(swap2(a), pk2(T.z, T.w), mul2(a, pk2(T.x, T.y)));
}
// RY 2x2 on a register pair (packed): u' = c*u - s*v ; v' = s*u + c*v
__device__ __forceinline__ void rotp2(u64& u, u64& v, u64 c2, u64 s2, u64 ns2) {
    u64 nu = fma2(v, ns2, mul2(u, c2));
    u64 nv = fma2(v, c2,  mul2(u, s2));
    u = nu; v = nv;
}

// Layouts:
//   L0: amplitude s = (h<<5)|lane   (reg h = bits 9..5, lane = bits 4..0)
//   L1: amplitude s = (lane<<5)|h   (lane = bits 9..5, reg h = bits 4..0)
// Shared swizzle: phys(s) = s ^ ((s>>5)&31)  -> conflict-free for all 4 patterns.
__global__ __launch_bounds__(NTHREADS, 3)
void qsim_kernel(const float* __restrict__ x, float* __restrict__ out) {
    __shared__ u64 stage[WPB][QDIM];

    const int lane = threadIdx.x & 31;
    const int wid  = threadIdx.x >> 5;
    const int b    = blockIdx.x * WPB + wid;
    u64* st = stage[wid];

    float xv[NW];
    #pragma unroll
    for (int w = 0; w < NW; ++w) xv[w] = __ldg(&x[b * NW + w]);

    // Per-thread gather constant: addr = D[h] ^ pladj
    const int pl    = perm_of(lane);
    const int pladj = pl ^ ((lane & 1) ? 0x18 : 0);

    // Encoding angle contribution from lane bits (wires 5..9)
    float langle = 0.f;
    #pragma unroll
    for (int w = 5; w < NW; ++w)
        langle += ((lane >> (9 - w)) & 1) ? -xv[w] : xv[w];

    // |0...0>  (s=0 -> lane 0, reg 0)
    u64 r[32];
    #pragma unroll
    for (int h = 0; h < 32; ++h) r[h] = 0ull;
    if (lane == 0) r[0] = pk2(1.f, 0.f);

    for (int k = 0; k < NBLK; ++k) {
        // --- diag A (L0): s = (h<<5)|lane ---
        #pragma unroll 8
        for (int h = 0; h < 32; ++h)
            r[h] = cmulT(r[h], __ldg(&gA[k][(h << 5) | lane]));

        #pragma unroll
        for (int sweep = 0; sweep < 2; ++sweep) {
            // L0 in-register wires: w = 0..4, reg-bit rb = 4-w
            #pragma unroll
            for (int rb = 0; rb < 5; ++rb) {
                float2 rc = gRy[k][sweep][4 - rb];
                u64 c2 = pk2(rc.x, rc.x), s2 = pk2(rc.y, rc.y), ns2 = pk2(-rc.y, -rc.y);
                #pragma unroll
                for (int h = 0; h < 32; ++h)
                    if (!(h & (1 << rb)))
                        rotp2(r[h], r[h | (1 << rb)], c2, s2, ns2);
            }
            // transpose L0 -> L1 through private warp stage
            __syncwarp();
            #pragma unroll
            for (int h = 0; h < 32; ++h)
                st[(h << 5) | (lane ^ h)] = r[h];
            __syncwarp();
            #pragma unroll
            for (int h = 0; h < 32; ++h)
                r[h] = st[(lane << 5) | (h ^ lane)];
            // L1 in-register wires: w = 5..9, reg-bit rb = 9-w
            #pragma unroll
            for (int rb = 0; rb < 5; ++rb) {
                float2 rc = gRy[k][sweep][9 - rb];
                u64 c2 = pk2(rc.x, rc.x), s2 = pk2(rc.y, rc.y), ns2 = pk2(-rc.y, -rc.y);
                #pragma unroll
                for (int h = 0; h < 32; ++h)
                    if (!(h & (1 << rb)))
                        rotp2(r[h], r[h | (1 << rb)], c2, s2, ns2);
            }
            // write (L1) -> gather by perm into L0, fused diag B (sweep0) / C (sweep1)
            __syncwarp();
            #pragma unroll
            for (int h = 0; h < 32; ++h)
                st[(lane << 5) | (h ^ lane)] = r[h];
            __syncwarp();
            const float4* __restrict__ T = (sweep == 0) ? gB[k] : gC[k];
            #pragma unroll 8
            for (int h = 0; h < 32; ++h) {
                const int C = perm_of(h << 5);            // compile-time
                const int D = C ^ ((C >> 5) & 31);        // compile-time
                u64 v = st[D ^ pladj];
                r[h] = cmulT(v, __ldg(&T[(h << 5) | lane]));
            }
        }

        // --- batch encoding phase (k < last), state in L0 ---
        if (k != NBLK - 1) {
            #pragma unroll 8
            for (int h = 0; h < 32; ++h) {
                float ang = langle;
                #pragma unroll
                for (int w = 0; w < 5; ++w)
                    ang += ((h >> (4 - w)) & 1) ? -xv[w] : xv[w];
                float c, si;
                __sincosf(-0.5f * ang, &si, &c);
                r[h] = fma2(swap2(r[h]), pk2(-si, si), mul2(r[h], pk2(c, c)));
            }
        }
    }

    // --- expectation values: out[b][w] = sum_s |a_s|^2 * z[w][s] ---
    float acc[NW];
    #pragma unroll
    for (int w = 0; w < NW; ++w) acc[w] = 0.f;
    float totP = 0.f;
    #pragma unroll
    for (int h = 0; h < 32; ++h) {
        float ax, ay; unpk2(r[h], ax, ay);
        float p = fmaf(ax, ax, ay * ay);
        totP += p;
        #pragma unroll
        for (int w = 0; w < 5; ++w)                     // wires 0..4 <- reg bits
            acc[w] += ((h >> (4 - w)) & 1) ? -p : p;
    }
    #pragma unroll
    for (int w = 5; w < NW; ++w)                        // wires 5..9 <- lane bits
        acc[w] = ((lane >> (9 - w)) & 1) ? -totP : totP;

    #pragma unroll
    for (int off = 16; off; off >>= 1)
        #pragma unroll
        for (int w = 0; w < NW; ++w)
            acc[w] += __shfl_xor_sync(0xffffffffu, acc[w], off);

    if (lane == 0) {
        #pragma unroll
        for (int w = 0; w < NW; ++w) out[b * NW + w] = acc[w];
    }
}

extern "C" void kernel_launch(void* const* d_in, const int* in_sizes, int n_in,
                              void* d_out, int out_size) {
    const float* x      = (const float*)d_in[0];
    const float* params = (const float*)d_in[1];
    float* out = (float*)d_out;
    int bsz = in_sizes[0] / NW;           // 2048
    precompute_kernel<<<1, QDIM>>>(params);
    qsim_kernel<<<bsz / WPB, NTHREADS>>>(x, out);
}